// round 17
// baseline (speedup 1.0000x reference)
#include <cuda_runtime.h>
#include <math.h>
#include <stdint.h>

#define BB 64
#define TD 128
#define TE 256
#define DX 1024
#define HH 1024
#define N3 3072

// ---------------- persistent state (device globals; no allocations) ----------------
__device__ __align__(16) float g_h[2][BB * HH];       // ping-pong GRU state
__device__ __align__(16) float g_ifeed[BB * HH];
__device__ __align__(16) float g_feed[BB * HH];
__device__ __align__(16) float g_value[BB * HH];
__device__ __align__(16) float g_fp[4][BB * HH];      // FEED k-split partials
__device__ __align__(16) float g_gxp[4][BB * N3];     // gx k-split partials
__device__ __align__(16) float g_ghp[4][BB * N3];     // gh k-split partials
__device__ __align__(16) float g_hattp[8][BB * HH];   // HATT partials
__device__ __align__(16) float g_attv[4][BB * HH];    // attention value partials
__device__ float g_attm[4][BB];
__device__ float g_atts[4][BB];
__device__ __align__(16) float g_gxx[(size_t)TD * BB * N3];  // 96MB

__global__ void init64(const float* __restrict__ h_enc) {
    int i = blockIdx.x * blockDim.x + threadIdx.x;
    if (i < BB * HH) { g_h[0][i] = h_enc[i]; g_ifeed[i] = 0.0f; }
}

__device__ __forceinline__ void ffma2(unsigned long long& a,
                                      unsigned long long x, unsigned long long y) {
    asm("fma.rn.f32x2 %0, %1, %2, %0;" : "+l"(a) : "l"(x), "l"(y));
}
__device__ __forceinline__ unsigned long long fadd2(unsigned long long x,
                                                    unsigned long long y) {
    unsigned long long d;
    asm("add.rn.f32x2 %0, %1, %2;" : "=l"(d) : "l"(x), "l"(y));
    return d;
}
__device__ __forceinline__ float lo2(unsigned long long v) {
    return __uint_as_float((unsigned)(v & 0xffffffffull));
}
__device__ __forceinline__ float hi2(unsigned long long v) {
    return __uint_as_float((unsigned)(v >> 32));
}

// ---------------- gk6: pipe-bound FFMA2 GEMM, C[64m x 32n] = A[64,K] @ W -----------
// 256 thr = 8 warps; warp kg = k-group (8-way in-block k-split over 32-k chunks,
// 4 k per warp per chunk). Lane: mg=lane&7 (m=8mg..8mg+7), ng=lane>>3 (n=8ng..8ng+7).
// Accs: n-paired f32x2, acc[8 m][4 n-pair] = 32 ULL (final values, no k-pair split).
// sA: per k, 64 m stored as DUPLICATED float2 (a,a), 16B chunks permuted
//     q' = ((q&3)<<3)|(q>>2)  so load j of lane mg hits chunk 8j+mg (conflict-free,
//     contiguous 128B per instr, 4-way ng-broadcast dedup).
// sW: per k, 16 n-pair float2, row 144B; 2xLDS.128 per thread, conflict-free.
// Per k per warp: 6 crossbar cyc vs 32 FFMA2 (64 SMSP cyc) -> FFMA2-pipe-bound.
#define AROW 528                      // bytes per k-row of sA (33 x 16B chunks)
#define WROW 144                      // bytes per k-row of sW (18 float2)
template <int MODE>
__global__ __launch_bounds__(256, 2)
void gk6(const float* __restrict__ pA, const float* __restrict__ pW,
         const float* __restrict__ pW2, const float* __restrict__ pBias, int hsel)
{
    constexpr int KW   = (MODE == 0) ? 1024 : 256;
    constexpr int CH   = KW / 32;
    constexpr int NDIM = (MODE == 0 || MODE == 2) ? N3 : HH;

    __shared__ __align__(16) char sA[2][32 * AROW];   // 33792 B
    __shared__ __align__(16) char sW[2][32 * WROW];   // 9216 B

    const int tid  = threadIdx.x;
    const int kg   = tid >> 5;
    const int lane = tid & 31;
    const int mg   = lane & 7;
    const int ng   = lane >> 3;
    const int n0   = blockIdx.x * 32;

    const float* A; size_t lda = HH;
    const float* W = pW;
    int kA = 0, kW2 = 0;
    float* C; size_t ldc;

    if (MODE == 0) {
        A = pA + (size_t)blockIdx.y * DX; lda = (size_t)TD * DX;
        C = g_gxx + (size_t)blockIdx.y * BB * N3; ldc = N3;
    } else if (MODE == 1) {
        const int z = blockIdx.y;
        A = g_ifeed; kA = kW2 = z * 256;
        C = g_fp[z]; ldc = HH;
    } else if (MODE == 2) {
        const int z = blockIdx.z;
        kA = kW2 = z * 256;
        if (blockIdx.y == 0) { A = g_feed;     W = pW;  C = g_gxp[z]; }
        else                 { A = g_h[hsel];  W = pW2; C = g_ghp[z]; }
        ldc = N3;
    } else {
        const int y = blockIdx.y, z = blockIdx.z;
        A = y ? g_h[hsel] : g_value;
        kA = z * 256; kW2 = y * HH + z * 256;
        C = g_hattp[y * 4 + z]; ldc = HH;
    }

    // staging registers
    float4 ra[2];
    float2 rw[2];
    const int am = (2 * 256 + tid) >> 3 & 63;  // dummy init suppress warnings
    (void)am;

    auto ldg = [&](int c) {
        const int kcA = kA + c * 32;
        #pragma unroll
        for (int it = 0; it < 2; ++it) {
            int idx = it * 256 + tid;
            int m = idx >> 3, kq = idx & 7;
            ra[it] = *reinterpret_cast<const float4*>(
                A + (size_t)m * lda + kcA + kq * 4);
        }
        const int kcW = kW2 + c * 32;
        #pragma unroll
        for (int it = 0; it < 2; ++it) {
            int idx = it * 256 + tid;
            int k = idx >> 4, np = idx & 15;
            rw[it] = *reinterpret_cast<const float2*>(
                W + (size_t)(kcW + k) * NDIM + n0 + 2 * np);
        }
    };
    auto sts = [&](int buf) {
        char* a = sA[buf];
        char* w = sW[buf];
        #pragma unroll
        for (int it = 0; it < 2; ++it) {
            int idx = it * 256 + tid;
            int m = idx >> 3, kq = idx & 7;
            int q = m >> 1, sub = m & 1;
            int qp = ((q & 3) << 3) | (q >> 2);
            const float* rf = reinterpret_cast<const float*>(&ra[it]);
            #pragma unroll
            for (int j = 0; j < 4; ++j) {
                float v = rf[j];
                *reinterpret_cast<float2*>(a + (kq * 4 + j) * AROW + qp * 16 + sub * 8)
                    = make_float2(v, v);
            }
        }
        #pragma unroll
        for (int it = 0; it < 2; ++it) {
            int idx = it * 256 + tid;
            int k = idx >> 4, np = idx & 15;
            *reinterpret_cast<float2*>(w + k * WROW + np * 8) = rw[it];
        }
    };

    unsigned long long acc[8][4];
    #pragma unroll
    for (int mi = 0; mi < 8; ++mi)
        #pragma unroll
        for (int nj = 0; nj < 4; ++nj) acc[mi][nj] = 0ull;

    ldg(0); sts(0); __syncthreads();

    #pragma unroll 1
    for (int c = 0; c < CH; ++c) {
        if (c + 1 < CH) ldg(c + 1);
        const char* a = sA[c & 1];
        const char* w = sW[c & 1];
        #pragma unroll
        for (int kk = 0; kk < 4; ++kk) {
            const int k = kg * 4 + kk;
            const char* arow = a + k * AROW;
            const char* wrow = w + k * WROW;
            ulonglong2 A0 = *reinterpret_cast<const ulonglong2*>(arow + (0 + mg) * 16);
            ulonglong2 A1 = *reinterpret_cast<const ulonglong2*>(arow + (8 + mg) * 16);
            ulonglong2 A2 = *reinterpret_cast<const ulonglong2*>(arow + (16 + mg) * 16);
            ulonglong2 A3 = *reinterpret_cast<const ulonglong2*>(arow + (24 + mg) * 16);
            ulonglong2 W0 = *reinterpret_cast<const ulonglong2*>(wrow + ng * 32);
            ulonglong2 W1 = *reinterpret_cast<const ulonglong2*>(wrow + ng * 32 + 16);
            // load j gives dup pairs for m = 8mg+2j, 8mg+2j+1
            ffma2(acc[0][0], A0.x, W0.x); ffma2(acc[0][1], A0.x, W0.y);
            ffma2(acc[0][2], A0.x, W1.x); ffma2(acc[0][3], A0.x, W1.y);
            ffma2(acc[1][0], A0.y, W0.x); ffma2(acc[1][1], A0.y, W0.y);
            ffma2(acc[1][2], A0.y, W1.x); ffma2(acc[1][3], A0.y, W1.y);
            ffma2(acc[2][0], A1.x, W0.x); ffma2(acc[2][1], A1.x, W0.y);
            ffma2(acc[2][2], A1.x, W1.x); ffma2(acc[2][3], A1.x, W1.y);
            ffma2(acc[3][0], A1.y, W0.x); ffma2(acc[3][1], A1.y, W0.y);
            ffma2(acc[3][2], A1.y, W1.x); ffma2(acc[3][3], A1.y, W1.y);
            ffma2(acc[4][0], A2.x, W0.x); ffma2(acc[4][1], A2.x, W0.y);
            ffma2(acc[4][2], A2.x, W1.x); ffma2(acc[4][3], A2.x, W1.y);
            ffma2(acc[5][0], A2.y, W0.x); ffma2(acc[5][1], A2.y, W0.y);
            ffma2(acc[5][2], A2.y, W1.x); ffma2(acc[5][3], A2.y, W1.y);
            ffma2(acc[6][0], A3.x, W0.x); ffma2(acc[6][1], A3.x, W0.y);
            ffma2(acc[6][2], A3.x, W1.x); ffma2(acc[6][3], A3.x, W1.y);
            ffma2(acc[7][0], A3.y, W0.x); ffma2(acc[7][1], A3.y, W0.y);
            ffma2(acc[7][2], A3.y, W1.x); ffma2(acc[7][3], A3.y, W1.y);
        }
        if (c + 1 < CH) sts((c + 1) & 1);
        __syncthreads();
    }

    // ---- reduce 8 k-group warps (3 levels through smem; reuse sA) ----
    __syncthreads();   // everyone done reading sA
    unsigned long long* red = reinterpret_cast<unsigned long long*>(&sA[0][0]);
    #pragma unroll
    for (int r = 4; r >= 1; r >>= 1) {
        if (kg >= r && kg < 2 * r) {
            unsigned long long* d = red + (size_t)((kg - r) * 32 + lane) * 33;
            #pragma unroll
            for (int mi = 0; mi < 8; ++mi)
                #pragma unroll
                for (int nj = 0; nj < 4; ++nj) d[mi * 4 + nj] = acc[mi][nj];
        }
        __syncthreads();
        if (kg < r) {
            const unsigned long long* s = red + (size_t)(kg * 32 + lane) * 33;
            #pragma unroll
            for (int mi = 0; mi < 8; ++mi)
                #pragma unroll
                for (int nj = 0; nj < 4; ++nj)
                    acc[mi][nj] = fadd2(acc[mi][nj], s[mi * 4 + nj]);
        }
        __syncthreads();
    }

    // ---- epilogue: warp 0 stores float2 per (m, n-pair) ----
    if (kg == 0) {
        #pragma unroll
        for (int mi = 0; mi < 8; ++mi) {
            const int m = mg * 8 + mi;
            #pragma unroll
            for (int nj = 0; nj < 4; ++nj) {
                const int n = n0 + ng * 8 + 2 * nj;
                float2 v = make_float2(lo2(acc[mi][nj]), hi2(acc[mi][nj]));
                if (MODE == 0) {
                    float2 bb = *reinterpret_cast<const float2*>(pBias + n);
                    v.x += bb.x; v.y += bb.y;
                }
                *reinterpret_cast<float2*>(C + (size_t)m * ldc + n) = v;
            }
        }
    }
}

// ---------------- FEED combine ------------------------------------------------------
__global__ void feedcomb(const float* __restrict__ bfeed) {
    int idx = blockIdx.x * blockDim.x + threadIdx.x;
    int n = idx & 1023;
    g_feed[idx] = tanhf(g_fp[0][idx] + g_fp[1][idx] + g_fp[2][idx] + g_fp[3][idx]
                        + bfeed[n]);
}

// ---------------- fused GRU + partial attention (champion, verbatim) ----------------
__global__ __launch_bounds__(512)
void attnp(const float* __restrict__ o_enc, const float* __restrict__ bhr, int t)
{
    __shared__ __align__(16) float sh[HH];
    __shared__ float sp[64];
    __shared__ float red[8];

    const int b = blockIdx.x;
    const int z = blockIdx.y;
    const int tid = threadIdx.x;
    const int w = tid >> 5;
    const int l = tid & 31;
    const int hsel = t & 1;

    const float* gxx = g_gxx + (size_t)t * BB * N3 + (size_t)b * N3;
    const float* hcur = g_h[hsel];
    float* hnxt = g_h[hsel ^ 1];

    #pragma unroll
    for (int r = 0; r < 2; ++r) {
        int i = (r << 9) + tid;
        int i0 = b * N3 + i, i1 = i0 + HH, i2 = i0 + 2 * HH;
        float xz  = g_gxp[0][i0] + g_gxp[1][i0] + g_gxp[2][i0] + g_gxp[3][i0] + gxx[i];
        float xr  = g_gxp[0][i1] + g_gxp[1][i1] + g_gxp[2][i1] + g_gxp[3][i1] + gxx[HH + i];
        float xh  = g_gxp[0][i2] + g_gxp[1][i2] + g_gxp[2][i2] + g_gxp[3][i2] + gxx[2 * HH + i];
        float hz  = g_ghp[0][i0] + g_ghp[1][i0] + g_ghp[2][i0] + g_ghp[3][i0] + bhr[i];
        float hr  = g_ghp[0][i1] + g_ghp[1][i1] + g_ghp[2][i1] + g_ghp[3][i1] + bhr[HH + i];
        float hh2 = g_ghp[0][i2] + g_ghp[1][i2] + g_ghp[2][i2] + g_ghp[3][i2] + bhr[2 * HH + i];
        float hp  = hcur[b * HH + i];
        float zz = 1.0f / (1.0f + expf(-(xz + hz)));
        float rr = 1.0f / (1.0f + expf(-(xr + hr)));
        float hc = tanhf(xh + rr * hh2);
        float hn = zz * hp + (1.0f - zz) * hc;
        sh[i] = hn;
        if (z == 0) hnxt[b * HH + i] = hn;
    }
    __syncthreads();

    const float* ob = o_enc + (size_t)b * TE * HH;
    #pragma unroll
    for (int tt = 0; tt < 4; ++tt) {
        int tl = (w << 2) + tt;
        const float* orow = ob + (z * 64 + tl) * HH;
        float s = 0.0f;
        #pragma unroll
        for (int jj = 0; jj < 8; ++jj) {
            int i = (jj << 7) + (l << 2);
            float4 o4 = *reinterpret_cast<const float4*>(orow + i);
            float4 h4 = *reinterpret_cast<const float4*>(sh + i);
            s += o4.x * h4.x + o4.y * h4.y + o4.z * h4.z + o4.w * h4.w;
        }
        #pragma unroll
        for (int off = 16; off > 0; off >>= 1)
            s += __shfl_xor_sync(0xffffffffu, s, off);
        if (l == 0) sp[tl] = s;
    }
    __syncthreads();

    float v = 0.0f;
    if (tid < 64) {
        v = sp[tid];
        float M = v;
        #pragma unroll
        for (int off = 16; off > 0; off >>= 1)
            M = fmaxf(M, __shfl_xor_sync(0xffffffffu, M, off));
        if (l == 0) red[w] = M;
    }
    __syncthreads();
    const float M = fmaxf(red[0], red[1]);
    if (tid < 64) {
        float e = expf(v - M);
        float S = e;
        #pragma unroll
        for (int off = 16; off > 0; off >>= 1)
            S += __shfl_xor_sync(0xffffffffu, S, off);
        if (l == 0) red[2 + w] = S;
        sp[tid] = e;
    }
    __syncthreads();
    if (tid == 0) { g_attm[z][b] = M; g_atts[z][b] = red[2] + red[3]; }

    float2 a = make_float2(0.f, 0.f);
    const int col = tid << 1;
    const float* obz = ob + z * 64 * HH;
    #pragma unroll 4
    for (int te = 0; te < 64; ++te) {
        float pp = sp[te];
        float2 o2 = *reinterpret_cast<const float2*>(obz + te * HH + col);
        a.x = fmaf(pp, o2.x, a.x);
        a.y = fmaf(pp, o2.y, a.y);
    }
    *reinterpret_cast<float2*>(&g_attv[z][b * HH + col]) = a;
}

// ---------------- attention combine (champion) --------------------------------------
__global__ __launch_bounds__(512)
void attnc()
{
    const int b = blockIdx.x;
    const int tid = threadIdx.x;
    float m0 = g_attm[0][b], m1 = g_attm[1][b], m2 = g_attm[2][b], m3 = g_attm[3][b];
    float M = fmaxf(fmaxf(m0, m1), fmaxf(m2, m3));
    float c0 = expf(m0 - M), c1 = expf(m1 - M), c2 = expf(m2 - M), c3 = expf(m3 - M);
    float inv = 1.0f / (g_atts[0][b] * c0 + g_atts[1][b] * c1 +
                        g_atts[2][b] * c2 + g_atts[3][b] * c3);
    const int col = tid << 1;
    float2 v0 = *reinterpret_cast<const float2*>(&g_attv[0][b * HH + col]);
    float2 v1 = *reinterpret_cast<const float2*>(&g_attv[1][b * HH + col]);
    float2 v2 = *reinterpret_cast<const float2*>(&g_attv[2][b * HH + col]);
    float2 v3 = *reinterpret_cast<const float2*>(&g_attv[3][b * HH + col]);
    float2 r;
    r.x = (v0.x * c0 + v1.x * c1 + v2.x * c2 + v3.x * c3) * inv;
    r.y = (v0.y * c0 + v1.y * c1 + v2.y * c2 + v3.y * c3) * inv;
    *reinterpret_cast<float2*>(&g_value[b * HH + col]) = r;
}

// ---------------- HATT combine ------------------------------------------------------
__global__ void combine_hatt(float* __restrict__ out, const float* __restrict__ batt) {
    int idx = blockIdx.x * blockDim.x + threadIdx.x;
    int m = idx >> 10, n = idx & 1023;
    float v = g_hattp[0][idx] + g_hattp[1][idx] + g_hattp[2][idx] + g_hattp[3][idx]
            + g_hattp[4][idx] + g_hattp[5][idx] + g_hattp[6][idx] + g_hattp[7][idx]
            + batt[n];
    v = tanhf(v);
    out[(size_t)m * TD * HH + n] = v;
    g_ifeed[idx] = v;
}

// ---------------- launcher ----------------------------------------------------------
extern "C" void kernel_launch(void* const* d_in, const int* in_sizes, int n_in,
                              void* d_out, int out_size)
{
    const float* x      = (const float*)d_in[0];
    const float* o_enc  = (const float*)d_in[1];
    const float* h_enc  = (const float*)d_in[2];
    const float* Wfeed  = (const float*)d_in[3];
    const float* bfeed  = (const float*)d_in[4];
    const float* Wx     = (const float*)d_in[5];
    const float* Wh     = (const float*)d_in[6];
    const float* bxi    = (const float*)d_in[7];
    const float* bhr    = (const float*)d_in[8];
    const float* Watt   = (const float*)d_in[9];
    const float* batt   = (const float*)d_in[10];
    float* out = (float*)d_out;

    init64<<<64, 1024>>>(h_enc);

    // precompute g_gxx[t] = x_t @ Wx[1024:] + bxi (recurrence-independent)
    gk6<0><<<dim3(96, TD), 256>>>(x, Wx + (size_t)HH * N3, nullptr, bxi, 0);

    for (int t = 0; t < TD; ++t) {
        gk6<1><<<dim3(32, 4), 256>>>(nullptr, Wfeed, nullptr, nullptr, 0);
        feedcomb<<<128, 512>>>(bfeed);
        gk6<2><<<dim3(96, 2, 4), 256>>>(nullptr, Wx, Wh, nullptr, t & 1);
        attnp<<<dim3(BB, 4), 512>>>(o_enc, bhr, t);
        attnc<<<BB, 512>>>();
        gk6<3><<<dim3(32, 2, 4), 256>>>(nullptr, Watt, nullptr, nullptr, (t + 1) & 1);
        combine_hatt<<<128, 512>>>(out + (size_t)t * HH, batt);
    }
}